// round 17
// baseline (speedup 1.0000x reference)
#include <cuda_runtime.h>
#include <cstdint>

#define HID   32
#define NCOL  224
#define TPB   128     // 4 warps: w0={i,f} w1={z,ib} w2={fb,delta} w3={o}+combine
#define NSTEP 2047
#define NB    512
#define SEQ   2048
#define NTY   20
#define BETA  0.1f

typedef unsigned long long ull;

__device__ __forceinline__ unsigned su32(const void* p) {
    return (unsigned)__cvta_generic_to_shared(p);
}
__device__ __forceinline__ void ffma2(ull& d, ull a, ull b) {
    asm("fma.rn.f32x2 %0, %1, %2, %0;" : "+l"(d) : "l"(a), "l"(b));
}
__device__ __forceinline__ ull fadd2(ull a, ull b) {
    ull d; asm("add.rn.f32x2 %0, %1, %2;" : "=l"(d) : "l"(a), "l"(b)); return d;
}
__device__ __forceinline__ ull pack2(float a, float b) {
    ull d; asm("mov.b64 %0, {%1, %2};" : "=l"(d) : "f"(a), "f"(b)); return d;
}
__device__ __forceinline__ float sum2(ull v) {
    float a, b; asm("mov.b64 {%0, %1}, %2;" : "=f"(a), "=f"(b) : "l"(v));
    return a + b;
}
__device__ __forceinline__ void lds128(ull& a, ull& b, unsigned addr) {
    asm volatile("ld.shared.v2.u64 {%0, %1}, [%2];" : "=l"(a), "=l"(b) : "r"(addr));
}
// named-barrier producer/consumer (block = 128 threads)
__device__ __forceinline__ void bar_arrive(int id) {
    asm volatile("bar.arrive %0, 128;" :: "r"(id));
}
__device__ __forceinline__ void bar_sync(int id) {
    asm volatile("bar.sync %0, 128;" :: "r"(id) : "memory");
}

__device__ __forceinline__ float tanh_mufu(float x) {
    float y; asm("tanh.approx.f32 %0, %1;" : "=f"(y) : "f"(x)); return y;
}
__device__ __forceinline__ float sigmoid_mufu(float x) {
    return fmaf(tanh_mufu(0.5f * x), 0.5f, 0.5f);
}

__global__ __launch_bounds__(TPB, 4)
void hawkes_kernel(const int* __restrict__ types,
                   const float* __restrict__ dtime,
                   const float* __restrict__ emb,
                   const float* __restrict__ W,
                   const float* __restrict__ bvec,
                   float* __restrict__ out)
{
    __shared__ __align__(8) float2 s_gxp[NTY][TPB];   // pair-interleaved gx: {gxA, gxB} per thread
    __shared__ __align__(8) float2 s_actp[3 * HID];   // {i,f}[l], {z,ib}[32+l], {fb,edt}[64+l]
    __shared__ __align__(16) float s_h[HID];
    __shared__ unsigned char s_ty[NSTEP + 1];
    __shared__ float s_dt[NSTEP + 1];
    __shared__ float s_emb[NTY * HID];

    const int tid  = threadIdx.x;
    const int warp = tid >> 5;          // warp-uniform
    const int lane = tid & 31;
    const int bs   = blockIdx.x;

    // gate pair per warp: A gates {0,2,5,3}, B gates {1,4,6,-}
    const int gA = (warp == 0) ? 0 : (warp == 1) ? 2 : (warp == 2) ? 5 : 3;
    const int gB = (warp == 0) ? 1 : (warp == 1) ? 4 : 6;   // unused for warp3
    const bool has2 = (warp < 3);
    const int colA = gA * HID + lane;
    const int colB = gB * HID + lane;

    // ---- prologue ----
    for (int i = tid; i < NTY * HID; i += TPB) s_emb[i] = emb[i];
    for (int t = tid; t < NSTEP; t += TPB) {
        s_ty[t] = (unsigned char)types[bs * SEQ + t];
        s_dt[t] = dtime[bs * SEQ + t + 1];
    }
    if (tid == 0) { s_ty[NSTEP] = 0; s_dt[NSTEP] = 0.f; }
    if (tid < HID) s_h[tid] = 0.f;
    __syncthreads();

    // ---- gx pair table + packed recurrent weights ----
    {
        float wxa[HID], wxb[HID];
        #pragma unroll
        for (int k = 0; k < HID; k++) {
            wxa[k] = W[k * NCOL + colA];
            wxb[k] = has2 ? W[k * NCOL + colB] : 0.f;
        }
        const float ba = bvec[colA];
        const float bb = has2 ? bvec[colB] : 0.f;
        for (int ty = 0; ty < NTY; ty++) {
            float aa = ba, ab = bb;
            #pragma unroll
            for (int k = 0; k < HID; k++) {
                const float e = s_emb[ty * HID + k];
                aa += e * wxa[k];
                ab += e * wxb[k];
            }
            s_gxp[ty][tid] = make_float2(aa, ab);
        }
    }
    ull wA[HID / 2], wB[HID / 2];
    #pragma unroll
    for (int q = 0; q < HID / 2; q++) {
        wA[q] = pack2(W[(HID + 2 * q) * NCOL + colA],
                      W[(HID + 2 * q + 1) * NCOL + colA]);
        wB[q] = has2 ? pack2(W[(HID + 2 * q) * NCOL + colB],
                             W[(HID + 2 * q + 1) * NCOL + colB]) : 0ull;
    }
    __syncthreads();

    const unsigned hb = su32(s_h);
    float c = 0.f, cbar = 0.f;          // warp-3 combine state

    const size_t O1 = (size_t)NSTEP * NB * HID;
    size_t obase = (size_t)bs * HID + lane;

    float2 gx = s_gxp[(int)s_ty[0]][tid];   // prefetch t=0
    float  dtv = s_dt[0];

    for (int t = 0; t < NSTEP; t++) {
        // ---- matvec: both columns from one h broadcast (packed fp32x2) ----
        ull aA0 = 0, aA1 = 0, aB0 = 0, aB1 = 0;
        #pragma unroll
        for (int q = 0; q < 8; q++) {
            ull hA, hB;
            lds128(hA, hB, hb + q * 16);
            ffma2(aA0, hA, wA[2 * q]);
            ffma2(aA1, hB, wA[2 * q + 1]);
            if (has2) {
                ffma2(aB0, hA, wB[2 * q]);
                ffma2(aB1, hB, wB[2 * q + 1]);
            }
        }
        const float gAv = gx.x + sum2(fadd2(aA0, aA1));
        const float gBv = has2 ? (gx.y + sum2(fadd2(aB0, aB1))) : 0.f;
        const int tn = t + 1;

        if (warp == 3) {
            // ---- consumer: o_g in register, combine after sync(0) ----
            const float og = sigmoid_mufu(gAv);
            bar_sync(0);

            const float2 p0 = s_actp[lane];            // {i, f}
            const float2 p1 = s_actp[HID + lane];      // {z, ib}
            const float2 p2 = s_actp[2 * HID + lane];  // {fb, edt}

            const float cn  = fmaf(p0.y, c, p0.x * p1.x);
            const float cbn = fmaf(p2.x, cbar, p1.y * p1.x);
            const float ct  = fmaf(cn - cbn, p2.y, cbn);
            const float hn  = og * tanh_mufu(ct);
            c = ct; cbar = cbn;

            s_h[lane] = hn;
            bar_arrive(1);                              // release producers

            out[obase]          = hn;                   // h_out  (post-arrive)
            out[O1 + obase]     = cn;                   // c_out
            out[2 * O1 + obase] = cbn;                  // c_bar_out
            out[4 * O1 + obase] = og;                   // gate_out
            gx = s_gxp[(int)s_ty[tn]][tid];
            dtv = s_dt[tn];
        } else {
            // ---- producers: compute pair, publish one STS.64, arrive ----
            float aAct, bAct;
            float del = 0.f;
            if (warp == 0) {                            // i, f
                aAct = sigmoid_mufu(gAv);
                bAct = sigmoid_mufu(gBv);
            } else if (warp == 1) {                     // z, ib
                aAct = tanh_mufu(gAv);
                bAct = sigmoid_mufu(gBv);
            } else {                                    // fb, delta->edt
                aAct = sigmoid_mufu(gAv);
                const float y = BETA * gBv;
                del = (fmaxf(y, 0.f) + __logf(1.f + __expf(-fabsf(y)))) * (1.f / BETA);
                bAct = __expf(-del * dtv);              // publish exp(-delta*dt)
            }
            s_actp[warp * HID + lane] = make_float2(aAct, bAct);
            bar_arrive(0);
            if (warp == 2) out[3 * O1 + obase] = del;   // decay_out (post-arrive)
            gx = s_gxp[(int)s_ty[tn]][tid];
            dtv = s_dt[tn];
            bar_sync(1);                                // wait for h(t+1)
        }
        obase += (size_t)NB * HID;
    }
}

extern "C" void kernel_launch(void* const* d_in, const int* in_sizes, int n_in,
                              void* d_out, int out_size)
{
    const int*   types = (const int*)d_in[0];
    const float* dtime = (const float*)d_in[1];
    const float* emb   = (const float*)d_in[2];
    const float* W     = (const float*)d_in[3];
    const float* bvec  = (const float*)d_in[4];
    hawkes_kernel<<<NB, TPB>>>(types, dtime, emb, W, bvec, (float*)d_out);
}